// round 13
// baseline (speedup 1.0000x reference)
#include <cuda_runtime.h>
#include <cuda_bf16.h>
#include <math.h>
#include <stdint.h>

#define HDIM   256
#define BATCH  1024
#define TSTEPS 64
#define IMGD   2048
#define G4     1024
#define VOCAB  32000

// ---------------- device scratch (no allocation allowed) -------------------
__device__ float g_img[BATCH * HDIM];
__device__ float g_proj[(size_t)VOCAB * G4];                 // vocab projection (131MB)
__device__ __nv_bfloat16 g_ehi[(size_t)VOCAB * HDIM];
__device__ __nv_bfloat16 g_elo[(size_t)VOCAB * HDIM];
__device__ __nv_bfloat16 g_wih[G4 * 2 * HDIM];               // [p][0:256]=hi, [256:512]=lo
__device__ __nv_bfloat16 g_whh[G4 * 2 * HDIM];
__device__ float g_biasp[G4];
__device__ __nv_bfloat16 g_hhi[2][BATCH * HDIM];
__device__ __nv_bfloat16 g_hlo[2][BATCH * HDIM];

// ---------------- helpers ---------------------------------------------------
__device__ __forceinline__ uint32_t smem_u32(const void* p) {
    uint32_t a;
    asm("{ .reg .u64 t; cvta.to.shared.u64 t, %1; cvt.u32.u64 %0, t; }" : "=r"(a) : "l"(p));
    return a;
}
__device__ __forceinline__ void cp_async16(uint32_t saddr, const void* gaddr) {
    asm volatile("cp.async.cg.shared.global [%0], [%1], 16;" :: "r"(saddr), "l"(gaddr));
}
__device__ __forceinline__ void ldm_x4(uint32_t* r, uint32_t addr) {
    asm volatile("ldmatrix.sync.aligned.m8n8.x4.shared.b16 {%0,%1,%2,%3}, [%4];"
                 : "=r"(r[0]), "=r"(r[1]), "=r"(r[2]), "=r"(r[3]) : "r"(addr));
}
__device__ __forceinline__ void mma_bf16(float* d, const uint32_t* a, const uint32_t* b) {
    asm volatile("mma.sync.aligned.m16n8k16.row.col.f32.bf16.bf16.f32 "
                 "{%0,%1,%2,%3}, {%4,%5,%6,%7}, {%8,%9}, {%0,%1,%2,%3};"
                 : "+f"(d[0]), "+f"(d[1]), "+f"(d[2]), "+f"(d[3])
                 : "r"(a[0]), "r"(a[1]), "r"(a[2]), "r"(a[3]), "r"(b[0]), "r"(b[1]));
}

#define CLUSTER_ARRIVE() asm volatile("barrier.cluster.arrive.aligned;" ::: "memory")
#define CLUSTER_WAIT()   asm volatile("barrier.cluster.wait.aligned;" ::: "memory")

// ---------------- vocab-projection GEMM (bf16-split MMA) --------------------
// proj[32000,1024] = emb_all @ Wih'^T + biasp. CTA 128x128, 256 thr.
#define STG_BYTES 32768
#define XG_SMEM   (3 * STG_BYTES)

__global__ __launch_bounds__(256)
void proj_mma_kernel(float* __restrict__ Cout)
{
    extern __shared__ __align__(1024) char smem[];
    const uint32_t sbase = smem_u32(smem);
    const int t = threadIdx.x;
    const int lane = t & 31;
    const int wid = t >> 5;
    const int wm = wid >> 2;
    const int wn = wid & 3;
    const int m0 = blockIdx.x * 128;
    const int n0 = blockIdx.y * 128;

    const int lr = t >> 1;
    const int lhalf = t & 1;
    const __nv_bfloat16* a_hi = g_ehi + (size_t)(m0 + lr) * HDIM;
    const __nv_bfloat16* a_lo = g_elo + (size_t)(m0 + lr) * HDIM;
    const __nv_bfloat16* b_row = g_wih + (size_t)(n0 + lr) * (2 * HDIM);

    uint32_t sdst[4];
#pragma unroll
    for (int i = 0; i < 4; ++i) {
        const int w = lhalf * 4 + i;
        sdst[i] = (uint32_t)((lr * 8 + (w ^ (lr & 7))) * 16);
    }

    int rA[4], rB[4];
    const int mhi = lane >> 4;
    const int kq  = lane >> 3;          // 0..3: k-unit selector for B x4
#pragma unroll
    for (int mf = 0; mf < 4; ++mf)
        rA[mf] = wm * 64 + mf * 16 + ((lane >> 3) & 1) * 8 + (lane & 7);
#pragma unroll
    for (int q = 0; q < 4; ++q)
        rB[q] = wn * 32 + q * 8 + (lane & 7);

    float acc[4][4][4];
#pragma unroll
    for (int i = 0; i < 4; ++i)
#pragma unroll
        for (int j = 0; j < 4; ++j)
#pragma unroll
            for (int r = 0; r < 4; ++r) acc[i][j][r] = 0.f;

    auto issue = [&](int c, int s) {
        const int kcol = (c & 3) * 64;
        const __nv_bfloat16* asrc = (((c >> 2) == 1) ? a_lo : a_hi) + kcol;
        const __nv_bfloat16* bsrc = b_row + kcol + (((c >> 2) == 2) ? 256 : 0);
        const uint32_t sa = sbase + s * STG_BYTES;
        const uint32_t sb = sa + 16384;
#pragma unroll
        for (int i = 0; i < 4; ++i) {
            const int e = (lhalf * 4 + i) * 8;
            cp_async16(sa + sdst[i], asrc + e);
            cp_async16(sb + sdst[i], bsrc + e);
        }
        asm volatile("cp.async.commit_group;" ::: "memory");
    };

    issue(0, 0);
    issue(1, 1);

#pragma unroll 1
    for (int c = 0; c < 12; ++c) {
        if (c < 11) asm volatile("cp.async.wait_group 1;" ::: "memory");
        else        asm volatile("cp.async.wait_group 0;" ::: "memory");
        __syncthreads();
        if (c + 2 < 12) issue(c + 2, (c + 2) % 3);

        const uint32_t sa = sbase + (c % 3) * STG_BYTES;
        const uint32_t sb = sa + 16384;
#pragma unroll
        for (int ksp = 0; ksp < 2; ++ksp) {
            uint32_t bfr4[4][4];
#pragma unroll
            for (int q = 0; q < 4; ++q) {
                const int r = rB[q];
                ldm_x4(bfr4[q], sb + (uint32_t)((r * 8 + ((ksp * 4 + kq) ^ (r & 7))) * 16));
            }
#pragma unroll
            for (int ks2 = 0; ks2 < 2; ++ks2) {
                const int ks = ksp * 2 + ks2;
                uint32_t afr[4][4];
#pragma unroll
                for (int mf = 0; mf < 4; ++mf) {
                    const int r = rA[mf];
                    ldm_x4(afr[mf], sa + (uint32_t)((r * 8 + ((ks * 2 + mhi) ^ (r & 7))) * 16));
                }
#pragma unroll
                for (int mf = 0; mf < 4; ++mf)
#pragma unroll
                    for (int q = 0; q < 4; ++q)
                        mma_bf16(acc[mf][q], afr[mf], bfr4[q] + ks2 * 2);
            }
        }
    }

    const int mrow = m0 + wm * 64 + (lane >> 2);
    const int nco  = n0 + wn * 32 + (lane & 3) * 2;
#pragma unroll
    for (int q = 0; q < 4; ++q) {
        const float bp0 = g_biasp[nco + q * 8];
        const float bp1 = g_biasp[nco + q * 8 + 1];
#pragma unroll
        for (int mf = 0; mf < 4; ++mf) {
            const int m = mrow + mf * 16;
            float2 v0 = make_float2(acc[mf][q][0] + bp0, acc[mf][q][1] + bp1);
            float2 v1 = make_float2(acc[mf][q][2] + bp0, acc[mf][q][3] + bp1);
            *(float2*)&Cout[(size_t)m * G4 + nco + q * 8] = v0;
            *(float2*)&Cout[(size_t)(m + 8) * G4 + nco + q * 8] = v1;
        }
    }
}

// ---------------- persistent LSTM recurrence v7 -----------------------------
// 16 clusters of 8 CTAs (cluster = one mb row-group; nb = rank in cluster).
// Tile 64x128, 512 threads. Whh resident; h tile loaded per step; xg gathered
// from g_proj; c/img in registers. HW cluster barrier between steps, with the
// X prefetch issued in the arrive->wait window.
#define PB_BYTES 131072
#define PA_BYTES 65536
#define PX_BYTES 33792               // 64 rows * 132 floats (padded)
#define PS_SMEM  (PB_BYTES + PA_BYTES + PX_BYTES)

__global__ __launch_bounds__(512) __cluster_dims__(8, 1, 1)
void lstm_persist_kernel(const int* __restrict__ cap, float* __restrict__ out)
{
    extern __shared__ __align__(1024) char smem[];
    const uint32_t sbB = smem_u32(smem);
    const uint32_t sbA = sbB + PB_BYTES;
    const uint32_t sbX = sbA + PA_BYTES;
    float* sx = (float*)(smem + PB_BYTES + PA_BYTES);

    const int t = threadIdx.x;
    const int lane = t & 31;
    const int wid = t >> 5;
    const int wm = wid >> 2;           // 0..3 (16 rows each)
    const int wn = wid & 3;            // 0..3
    const int mb = blockIdx.x >> 3;    // cluster id  (16 groups)
    const int nb = blockIdx.x & 7;     // rank within cluster
    const int m0 = mb * 64;
    const int n0 = nb * 128;
    const int hcol = nb * 32;

    // ---- resident B: Whh permuted rows n0..n0+128, 512 cols (hi|lo) ----
#pragma unroll
    for (int i = 0; i < 16; ++i) {
        const int ug = i * 512 + t;
        const int r = ug >> 6, u = ug & 63;
        cp_async16(sbB + (uint32_t)((r * 64 + (u & ~7) + ((u & 7) ^ (r & 7))) * 16),
                   g_whh + (size_t)(n0 + r) * 512 + u * 8);
    }
    asm volatile("cp.async.commit_group;" ::: "memory");

    const int mhi = lane >> 4;
    const int kq  = lane >> 3;          // 0..3: k-unit selector for B x4
    const int rA = wm * 16 + ((lane >> 3) & 1) * 8 + (lane & 7);
    int rB[4];
#pragma unroll
    for (int q = 0; q < 4; ++q)
        rB[q] = q * 32 + wn * 8 + (lane & 7);

    const int jl0 = wn * 8 + (lane & 3) * 2;

    // ---- per-thread state: c (zeros) and img (4 cells) ----
    float creg[2][2];
    float img_r[2][2];
#pragma unroll
    for (int h = 0; h < 2; ++h) {
        const int m = m0 + wm * 16 + (lane >> 2) + h * 8;
        creg[h][0] = 0.f; creg[h][1] = 0.f;
        img_r[h][0] = g_img[m * HDIM + hcol + jl0];
        img_r[h][1] = g_img[m * HDIM + hcol + jl0 + 1];
    }

    // xg prefetch (gathered proj rows); X tile 64x128 fp32 padded to 132
    auto issueX = [&](int ts) {
        const int* capt = cap + ts * BATCH + m0;
#pragma unroll
        for (int i = 0; i < 4; ++i) {
            const int ug = i * 512 + t;
            const int r = ug >> 5, w = ug & 31;
            const int ci = __ldg(capt + r);
            cp_async16(sbX + (uint32_t)(r * 528 + w * 16),
                       g_proj + (size_t)ci * G4 + n0 + w * 4);
        }
        asm volatile("cp.async.commit_group;" ::: "memory");
    };

    issueX(0);

    asm volatile("cp.async.wait_group 1;" ::: "memory");  // B resident
    __syncthreads();

#pragma unroll 1
    for (int ts = 0; ts < TSTEPS; ++ts) {
        const __nv_bfloat16* hhi_r = g_hhi[ts & 1];
        const __nv_bfloat16* hlo_r = g_hlo[ts & 1];
        __nv_bfloat16* hhi_w = g_hhi[(ts & 1) ^ 1];
        __nv_bfloat16* hlo_w = g_hlo[(ts & 1) ^ 1];
        float* out_t = out + (size_t)ts * BATCH * HDIM;

        if (ts) CLUSTER_WAIT();   // peers' h(ts-1) stores now visible

        // ---- load whole A (h hi+lo, 64x256) ----
#pragma unroll
        for (int i = 0; i < 8; ++i) {
            const int ug = i * 512 + t;
            const int buf = ug >> 11;
            const int idx = ug & 2047;
            const int r = idx >> 5, u = idx & 31;
            const __nv_bfloat16* src = (buf ? hlo_r : hhi_r) + (size_t)(m0 + r) * HDIM + u * 8;
            cp_async16(sbA + (uint32_t)(buf * 32768 + (r * 32 + (u & ~7) + ((u & 7) ^ (r & 7))) * 16), src);
        }
        asm volatile("cp.async.commit_group;" ::: "memory");
        asm volatile("cp.async.wait_group 0;" ::: "memory");   // A + outstanding X
        __syncthreads();

        float acc[4][4];
#pragma unroll
        for (int j = 0; j < 4; ++j)
#pragma unroll
            for (int r = 0; r < 4; ++r) acc[j][r] = 0.f;

        // ---- sync-free MMA loop: B x4 paired fragments, 3 split terms ----
#pragma unroll 1
        for (int kc = 0; kc < 4; ++kc) {
#pragma unroll
            for (int ksp = 0; ksp < 2; ++ksp) {
                uint32_t bhi[4][4], blo[4][4];
#pragma unroll
                for (int q = 0; q < 4; ++q) {
                    const int r = rB[q];
                    const uint32_t sw = (uint32_t)(((ksp * 4 + kq) ^ (r & 7)) * 16);
                    ldm_x4(bhi[q], sbB + (uint32_t)((r * 64 + kc * 8) * 16) + sw);
                    ldm_x4(blo[q], sbB + (uint32_t)((r * 64 + 32 + kc * 8) * 16) + sw);
                }
#pragma unroll
                for (int ks2 = 0; ks2 < 2; ++ks2) {
                    const int ks = ksp * 2 + ks2;
                    uint32_t ahi[4], alo[4];
                    const uint32_t aoff = (uint32_t)((rA * 32 + kc * 8 + ((ks * 2 + mhi) ^ (rA & 7))) * 16);
                    ldm_x4(ahi, sbA + aoff);
                    ldm_x4(alo, sbA + 32768 + aoff);
#pragma unroll
                    for (int q = 0; q < 4; ++q) {
                        mma_bf16(acc[q], ahi, bhi[q] + ks2 * 2);
                        mma_bf16(acc[q], alo, bhi[q] + ks2 * 2);
                        mma_bf16(acc[q], ahi, blo[q] + ks2 * 2);
                    }
                }
            }
        }

        // ---- fused LSTM cell epilogue ----
#pragma unroll
        for (int h = 0; h < 2; ++h) {
            const int m = m0 + wm * 16 + (lane >> 2) + h * 8;
            const float* xr = sx + (m - m0) * 132;
            float hn[2];
#pragma unroll
            for (int jj = 0; jj < 2; ++jj) {
                const int jl = jl0 + jj;
                const int rs = h * 2 + jj;
                const float gi = acc[0][rs] + xr[jl];
                const float gf = acc[1][rs] + xr[32 + jl];
                const float gg = acc[2][rs] + xr[64 + jl];
                const float go = acc[3][rs] + xr[96 + jl];
                const float iv = 1.f / (1.f + expf(-gi));
                const float fv = 1.f / (1.f + expf(-gf));
                const float gv = tanhf(gg);
                const float ov = 1.f / (1.f + expf(-go));
                const float cn = fv * creg[h][jj] + iv * gv;
                hn[jj] = ov * tanhf(cn);
                creg[h][jj] = cn;
            }
            const int idx = m * HDIM + hcol + jl0;
            const __nv_bfloat16 h0 = __float2bfloat16(hn[0]);
            const __nv_bfloat16 h1 = __float2bfloat16(hn[1]);
            __nv_bfloat162 hhp; hhp.x = h0; hhp.y = h1;
            __nv_bfloat162 hlp;
            hlp.x = __float2bfloat16(hn[0] - __bfloat162float(h0));
            hlp.y = __float2bfloat16(hn[1] - __bfloat162float(h1));
            *(__nv_bfloat162*)&hhi_w[idx] = hhp;
            *(__nv_bfloat162*)&hlo_w[idx] = hlp;
            float2 ov2 = make_float2(hn[0] + img_r[h][0], hn[1] + img_r[h][1]);
            *(float2*)&out_t[idx] = ov2;
        }

        if (ts + 1 < TSTEPS) {
            __syncthreads();       // all threads' h stores + sx reads done
            __threadfence();       // release h stores to cluster peers
            CLUSTER_ARRIVE();
            issueX(ts + 1);        // static prefetch inside the skew window
        }
    }
}

// ---------------- all prepacking in ONE kernel -------------------------------
#define S_EMB  ((size_t)VOCAB * HDIM)
#define S_W    ((size_t)G4 * HDIM)
#define S_HC   ((size_t)BATCH * HDIM)
#define PREP_TOTAL (S_EMB + 2 * S_W + S_HC + G4)

__global__ void prep_all_kernel(const float* __restrict__ emb,
                                const float* __restrict__ Wih,
                                const float* __restrict__ Whh,
                                const float* __restrict__ bih,
                                const float* __restrict__ bhh)
{
    const size_t i = (size_t)blockIdx.x * 256 + threadIdx.x;
    if (i < S_EMB) {
        const float v = emb[i];
        const __nv_bfloat16 h = __float2bfloat16(v);
        g_ehi[i] = h;
        g_elo[i] = __float2bfloat16(v - __bfloat162float(h));
    } else if (i < S_EMB + 2 * S_W) {
        const size_t ii = i - S_EMB;
        const int which = (int)(ii / S_W);
        const int idx = (int)(ii % S_W);
        const int p = idx >> 8, k = idx & 255;
        const int nt = p >> 7, q = (p >> 5) & 3, j = p & 31;
        const int orig = q * 256 + nt * 32 + j;
        const float* W = which ? Whh : Wih;
        __nv_bfloat16* Wd = which ? g_whh : g_wih;
        const float v = W[orig * 256 + k];
        const __nv_bfloat16 h = __float2bfloat16(v);
        Wd[p * 512 + k] = h;
        Wd[p * 512 + 256 + k] = __float2bfloat16(v - __bfloat162float(h));
    } else if (i < S_EMB + 2 * S_W + S_HC) {
        const int idx = (int)(i - S_EMB - 2 * S_W);
        g_hhi[0][idx] = __float2bfloat16(0.f);
        g_hlo[0][idx] = __float2bfloat16(0.f);
    } else if (i < PREP_TOTAL) {
        const int p = (int)(i - S_EMB - 2 * S_W - S_HC);
        const int nt = p >> 7, q = (p >> 5) & 3, j = p & 31;
        const int orig = q * 256 + nt * 32 + j;
        g_biasp[p] = bih[orig] + bhh[orig];
    }
}

// ---------------- fp32 image GEMM (small) ------------------------------------
__global__ __launch_bounds__(256)
void img_gemm_kernel(const float* __restrict__ A, const float* __restrict__ Bm,
                     float* __restrict__ C, const float* __restrict__ bias)
{
    const int N = HDIM, K = IMGD;
    __shared__ float As[16][64];
    __shared__ float Bs[16][64];
    const int tid = threadIdx.x;
    const int tx = tid & 15, ty = tid >> 4;
    const int m0 = blockIdx.x * 64, n0 = blockIdx.y * 64;
    const int lrow = tid >> 2, lcol4 = (tid & 3) * 4;
    const float* aptr = A + (size_t)(m0 + lrow) * K;
    const float* bptr = Bm + (size_t)(n0 + lrow) * K;
    float acc[4][4];
#pragma unroll
    for (int i = 0; i < 4; i++)
#pragma unroll
        for (int j = 0; j < 4; j++) acc[i][j] = 0.f;
    for (int k0 = 0; k0 < K; k0 += 16) {
        float4 av = *(const float4*)(aptr + k0 + lcol4);
        float4 bv = *(const float4*)(bptr + k0 + lcol4);
        As[lcol4 + 0][lrow] = av.x; As[lcol4 + 1][lrow] = av.y;
        As[lcol4 + 2][lrow] = av.z; As[lcol4 + 3][lrow] = av.w;
        Bs[lcol4 + 0][lrow] = bv.x; Bs[lcol4 + 1][lrow] = bv.y;
        Bs[lcol4 + 2][lrow] = bv.z; Bs[lcol4 + 3][lrow] = bv.w;
        __syncthreads();
#pragma unroll
        for (int k = 0; k < 16; k++) {
            float a[4], b[4];
            *(float4*)a = *(const float4*)&As[k][ty * 4];
            *(float4*)b = *(const float4*)&Bs[k][tx * 4];
#pragma unroll
            for (int i = 0; i < 4; i++)
#pragma unroll
                for (int j = 0; j < 4; j++) acc[i][j] = fmaf(a[i], b[j], acc[i][j]);
        }
        __syncthreads();
    }
#pragma unroll
    for (int i = 0; i < 4; i++)
#pragma unroll
        for (int j = 0; j < 4; j++)
            C[(size_t)(m0 + ty * 4 + i) * N + n0 + tx * 4 + j] =
                fmaxf(acc[i][j] + bias[n0 + tx * 4 + j], 0.f);
}

// ---------------- launcher ---------------------------------------------------
extern "C" void kernel_launch(void* const* d_in, const int* in_sizes, int n_in,
                              void* d_out, int out_size)
{
    const float* img  = (const float*)d_in[0];
    const int*   cap  = (const int*)  d_in[1];
    const float* Wimg = (const float*)d_in[2];
    const float* bimg = (const float*)d_in[3];
    const float* emb  = (const float*)d_in[4];
    const float* Wih  = (const float*)d_in[5];
    const float* Whh  = (const float*)d_in[6];
    const float* bih  = (const float*)d_in[7];
    const float* bhh  = (const float*)d_in[8];
    float* out = (float*)d_out;

    float* p_img;  cudaGetSymbolAddress((void**)&p_img,  g_img);
    float* p_proj; cudaGetSymbolAddress((void**)&p_proj, g_proj);

    cudaFuncSetAttribute(proj_mma_kernel, cudaFuncAttributeMaxDynamicSharedMemorySize, XG_SMEM);
    cudaFuncSetAttribute(lstm_persist_kernel, cudaFuncAttributeMaxDynamicSharedMemorySize, PS_SMEM);

    prep_all_kernel<<<(int)((PREP_TOTAL + 255) / 256), 256>>>(emb, Wih, Whh, bih, bhh);

    {
        dim3 grid(BATCH / 64, HDIM / 64);
        img_gemm_kernel<<<grid, 256>>>(img, Wimg, p_img, bimg);
    }

    {
        dim3 grid(VOCAB / 128, G4 / 128);   // 250 x 8
        proj_mma_kernel<<<grid, 256, XG_SMEM>>>(p_proj);
    }

    lstm_persist_kernel<<<128, 512, PS_SMEM>>>(cap, out);
}

// round 14
// speedup vs baseline: 1.5678x; 1.5678x over previous
#include <cuda_runtime.h>
#include <cuda_bf16.h>
#include <math.h>
#include <stdint.h>

#define HDIM   256
#define BATCH  1024
#define TSTEPS 64
#define IMGD   2048
#define G4     1024
#define VOCAB  32000

// ---------------- device scratch (no allocation allowed) -------------------
__device__ float g_img[BATCH * HDIM];
__device__ float g_imgpart[4 * BATCH * HDIM];                // split-K partials
__device__ float g_proj[(size_t)VOCAB * G4];                 // vocab projection (131MB)
__device__ __nv_bfloat16 g_ehi[(size_t)VOCAB * HDIM];
__device__ __nv_bfloat16 g_elo[(size_t)VOCAB * HDIM];
__device__ __nv_bfloat16 g_ihi[(size_t)BATCH * IMGD];
__device__ __nv_bfloat16 g_ilo[(size_t)BATCH * IMGD];
__device__ __nv_bfloat16 g_wimgp[HDIM * 2 * IMGD];           // [n][0:2048]=hi,[2048:4096]=lo
__device__ __nv_bfloat16 g_wih[G4 * 2 * HDIM];               // [p][0:256]=hi, [256:512]=lo
__device__ __nv_bfloat16 g_whh[G4 * 2 * HDIM];
__device__ float g_biasp[G4];
__device__ __nv_bfloat16 g_hhi[2][BATCH * HDIM];
__device__ __nv_bfloat16 g_hlo[2][BATCH * HDIM];

// grid-barrier state (proven primitive)
__device__ int g_bar_count;
__device__ volatile unsigned g_bar_gen;

// ---------------- helpers ---------------------------------------------------
__device__ __forceinline__ uint32_t smem_u32(const void* p) {
    uint32_t a;
    asm("{ .reg .u64 t; cvta.to.shared.u64 t, %1; cvt.u32.u64 %0, t; }" : "=r"(a) : "l"(p));
    return a;
}
__device__ __forceinline__ void cp_async16(uint32_t saddr, const void* gaddr) {
    asm volatile("cp.async.cg.shared.global [%0], [%1], 16;" :: "r"(saddr), "l"(gaddr));
}
__device__ __forceinline__ void ldm_x4(uint32_t* r, uint32_t addr) {
    asm volatile("ldmatrix.sync.aligned.m8n8.x4.shared.b16 {%0,%1,%2,%3}, [%4];"
                 : "=r"(r[0]), "=r"(r[1]), "=r"(r[2]), "=r"(r[3]) : "r"(addr));
}
__device__ __forceinline__ void mma_bf16(float* d, const uint32_t* a, const uint32_t* b) {
    asm volatile("mma.sync.aligned.m16n8k16.row.col.f32.bf16.bf16.f32 "
                 "{%0,%1,%2,%3}, {%4,%5,%6,%7}, {%8,%9}, {%0,%1,%2,%3};"
                 : "+f"(d[0]), "+f"(d[1]), "+f"(d[2]), "+f"(d[3])
                 : "r"(a[0]), "r"(a[1]), "r"(a[2]), "r"(a[3]), "r"(b[0]), "r"(b[1]));
}

// proven grid barrier (R5/R7/R8/R12)
__device__ __forceinline__ void grid_barrier() {
    __threadfence();
    __syncthreads();
    if (threadIdx.x == 0) {
        unsigned gen = g_bar_gen;
        if (atomicAdd(&g_bar_count, 1) == (int)gridDim.x - 1) {
            g_bar_count = 0;
            __threadfence();
            g_bar_gen = gen + 1;
        } else {
            while (g_bar_gen == gen) __nanosleep(32);
        }
        __threadfence();
    }
    __syncthreads();
}

// ---------------- vocab-projection GEMM (bf16-split MMA, R12) ---------------
#define STG_BYTES 32768
#define XG_SMEM   (3 * STG_BYTES)

__global__ __launch_bounds__(256)
void proj_mma_kernel(float* __restrict__ Cout)
{
    extern __shared__ __align__(1024) char smem[];
    const uint32_t sbase = smem_u32(smem);
    const int t = threadIdx.x;
    const int lane = t & 31;
    const int wid = t >> 5;
    const int wm = wid >> 2;
    const int wn = wid & 3;
    const int m0 = blockIdx.x * 128;
    const int n0 = blockIdx.y * 128;

    const int lr = t >> 1;
    const int lhalf = t & 1;
    const __nv_bfloat16* a_hi = g_ehi + (size_t)(m0 + lr) * HDIM;
    const __nv_bfloat16* a_lo = g_elo + (size_t)(m0 + lr) * HDIM;
    const __nv_bfloat16* b_row = g_wih + (size_t)(n0 + lr) * (2 * HDIM);

    uint32_t sdst[4];
#pragma unroll
    for (int i = 0; i < 4; ++i) {
        const int w = lhalf * 4 + i;
        sdst[i] = (uint32_t)((lr * 8 + (w ^ (lr & 7))) * 16);
    }

    int rA[4], rB[4];
    const int mhi = lane >> 4;
    const int kq  = lane >> 3;
#pragma unroll
    for (int mf = 0; mf < 4; ++mf)
        rA[mf] = wm * 64 + mf * 16 + ((lane >> 3) & 1) * 8 + (lane & 7);
#pragma unroll
    for (int q = 0; q < 4; ++q)
        rB[q] = wn * 32 + q * 8 + (lane & 7);

    float acc[4][4][4];
#pragma unroll
    for (int i = 0; i < 4; ++i)
#pragma unroll
        for (int j = 0; j < 4; ++j)
#pragma unroll
            for (int r = 0; r < 4; ++r) acc[i][j][r] = 0.f;

    auto issue = [&](int c, int s) {
        const int kcol = (c & 3) * 64;
        const __nv_bfloat16* asrc = (((c >> 2) == 1) ? a_lo : a_hi) + kcol;
        const __nv_bfloat16* bsrc = b_row + kcol + (((c >> 2) == 2) ? 256 : 0);
        const uint32_t sa = sbase + s * STG_BYTES;
        const uint32_t sb = sa + 16384;
#pragma unroll
        for (int i = 0; i < 4; ++i) {
            const int e = (lhalf * 4 + i) * 8;
            cp_async16(sa + sdst[i], asrc + e);
            cp_async16(sb + sdst[i], bsrc + e);
        }
        asm volatile("cp.async.commit_group;" ::: "memory");
    };

    issue(0, 0);
    issue(1, 1);

#pragma unroll 1
    for (int c = 0; c < 12; ++c) {
        if (c < 11) asm volatile("cp.async.wait_group 1;" ::: "memory");
        else        asm volatile("cp.async.wait_group 0;" ::: "memory");
        __syncthreads();
        if (c + 2 < 12) issue(c + 2, (c + 2) % 3);

        const uint32_t sa = sbase + (c % 3) * STG_BYTES;
        const uint32_t sb = sa + 16384;
#pragma unroll
        for (int ksp = 0; ksp < 2; ++ksp) {
            uint32_t bfr4[4][4];
#pragma unroll
            for (int q = 0; q < 4; ++q) {
                const int r = rB[q];
                ldm_x4(bfr4[q], sb + (uint32_t)((r * 8 + ((ksp * 4 + kq) ^ (r & 7))) * 16));
            }
#pragma unroll
            for (int ks2 = 0; ks2 < 2; ++ks2) {
                const int ks = ksp * 2 + ks2;
                uint32_t afr[4][4];
#pragma unroll
                for (int mf = 0; mf < 4; ++mf) {
                    const int r = rA[mf];
                    ldm_x4(afr[mf], sa + (uint32_t)((r * 8 + ((ks * 2 + mhi) ^ (r & 7))) * 16));
                }
#pragma unroll
                for (int mf = 0; mf < 4; ++mf)
#pragma unroll
                    for (int q = 0; q < 4; ++q)
                        mma_bf16(acc[mf][q], afr[mf], bfr4[q] + ks2 * 2);
            }
        }
    }

    const int mrow = m0 + wm * 64 + (lane >> 2);
    const int nco  = n0 + wn * 32 + (lane & 3) * 2;
#pragma unroll
    for (int q = 0; q < 4; ++q) {
        const float bp0 = g_biasp[nco + q * 8];
        const float bp1 = g_biasp[nco + q * 8 + 1];
#pragma unroll
        for (int mf = 0; mf < 4; ++mf) {
            const int m = mrow + mf * 16;
            float2 v0 = make_float2(acc[mf][q][0] + bp0, acc[mf][q][1] + bp1);
            float2 v1 = make_float2(acc[mf][q][2] + bp0, acc[mf][q][3] + bp1);
            *(float2*)&Cout[(size_t)m * G4 + nco + q * 8] = v0;
            *(float2*)&Cout[(size_t)(m + 8) * G4 + nco + q * 8] = v1;
        }
    }
}

// ---------------- img GEMM: bf16-split MMA, split-K over 4 slices -----------
// part[z][1024][256] = img_slice @ Wimg_slice^T (3 split terms, K=512/slice)
__global__ __launch_bounds__(256)
void img_mma_kernel(float* __restrict__ Cpart)
{
    extern __shared__ __align__(1024) char smem[];
    const uint32_t sbase = smem_u32(smem);
    const int t = threadIdx.x;
    const int lane = t & 31;
    const int wid = t >> 5;
    const int wm = wid >> 2;
    const int wn = wid & 3;
    const int m0 = blockIdx.x * 128;    // 8
    const int n0 = blockIdx.y * 128;    // 2
    const int kb = blockIdx.z * 512;    // 4 slices

    const int lr = t >> 1;
    const int lhalf = t & 1;
    const __nv_bfloat16* a_hi = g_ihi + (size_t)(m0 + lr) * IMGD + kb;
    const __nv_bfloat16* a_lo = g_ilo + (size_t)(m0 + lr) * IMGD + kb;
    const __nv_bfloat16* b_row = g_wimgp + (size_t)(n0 + lr) * (2 * IMGD) + kb;

    uint32_t sdst[4];
#pragma unroll
    for (int i = 0; i < 4; ++i) {
        const int w = lhalf * 4 + i;
        sdst[i] = (uint32_t)((lr * 8 + (w ^ (lr & 7))) * 16);
    }

    int rA[4], rB[4];
    const int mhi = lane >> 4;
    const int kq  = lane >> 3;
#pragma unroll
    for (int mf = 0; mf < 4; ++mf)
        rA[mf] = wm * 64 + mf * 16 + ((lane >> 3) & 1) * 8 + (lane & 7);
#pragma unroll
    for (int q = 0; q < 4; ++q)
        rB[q] = wn * 32 + q * 8 + (lane & 7);

    float acc[4][4][4];
#pragma unroll
    for (int i = 0; i < 4; ++i)
#pragma unroll
        for (int j = 0; j < 4; ++j)
#pragma unroll
            for (int r = 0; r < 4; ++r) acc[i][j][r] = 0.f;

    // 24 chunks: term = c/8 (0 hi*hi, 1 lo*hi, 2 hi*lo), kcol = (c%8)*64
    auto issue = [&](int c, int s) {
        const int term = c >> 3;
        const int kcol = (c & 7) * 64;
        const __nv_bfloat16* asrc = ((term == 1) ? a_lo : a_hi) + kcol;
        const __nv_bfloat16* bsrc = b_row + kcol + ((term == 2) ? IMGD : 0);
        const uint32_t sa = sbase + s * STG_BYTES;
        const uint32_t sb = sa + 16384;
#pragma unroll
        for (int i = 0; i < 4; ++i) {
            const int e = (lhalf * 4 + i) * 8;
            cp_async16(sa + sdst[i], asrc + e);
            cp_async16(sb + sdst[i], bsrc + e);
        }
        asm volatile("cp.async.commit_group;" ::: "memory");
    };

    issue(0, 0);
    issue(1, 1);

#pragma unroll 1
    for (int c = 0; c < 24; ++c) {
        if (c < 23) asm volatile("cp.async.wait_group 1;" ::: "memory");
        else        asm volatile("cp.async.wait_group 0;" ::: "memory");
        __syncthreads();
        if (c + 2 < 24) issue(c + 2, (c + 2) % 3);

        const uint32_t sa = sbase + (c % 3) * STG_BYTES;
        const uint32_t sb = sa + 16384;
#pragma unroll
        for (int ksp = 0; ksp < 2; ++ksp) {
            uint32_t bfr4[4][4];
#pragma unroll
            for (int q = 0; q < 4; ++q) {
                const int r = rB[q];
                ldm_x4(bfr4[q], sb + (uint32_t)((r * 8 + ((ksp * 4 + kq) ^ (r & 7))) * 16));
            }
#pragma unroll
            for (int ks2 = 0; ks2 < 2; ++ks2) {
                const int ks = ksp * 2 + ks2;
                uint32_t afr[4][4];
#pragma unroll
                for (int mf = 0; mf < 4; ++mf) {
                    const int r = rA[mf];
                    ldm_x4(afr[mf], sa + (uint32_t)((r * 8 + ((ks * 2 + mhi) ^ (r & 7))) * 16));
                }
#pragma unroll
                for (int mf = 0; mf < 4; ++mf)
#pragma unroll
                    for (int q = 0; q < 4; ++q)
                        mma_bf16(acc[mf][q], afr[mf], bfr4[q] + ks2 * 2);
            }
        }
    }

    float* cp = Cpart + (size_t)blockIdx.z * BATCH * HDIM;
    const int mrow = m0 + wm * 64 + (lane >> 2);
    const int nco  = n0 + wn * 32 + (lane & 3) * 2;
#pragma unroll
    for (int q = 0; q < 4; ++q) {
#pragma unroll
        for (int mf = 0; mf < 4; ++mf) {
            const int m = mrow + mf * 16;
            float2 v0 = make_float2(acc[mf][q][0], acc[mf][q][1]);
            float2 v1 = make_float2(acc[mf][q][2], acc[mf][q][3]);
            *(float2*)&cp[(size_t)m * HDIM + nco + q * 8] = v0;
            *(float2*)&cp[(size_t)(m + 8) * HDIM + nco + q * 8] = v1;
        }
    }
}

__global__ void img_reduce_kernel(const float* __restrict__ bimg)
{
    const int i = blockIdx.x * 256 + threadIdx.x;   // 0 .. BATCH*HDIM-1
    const int n = i & (HDIM - 1);
    float s = g_imgpart[i] + g_imgpart[BATCH * HDIM + i]
            + g_imgpart[2 * BATCH * HDIM + i] + g_imgpart[3 * BATCH * HDIM + i];
    g_img[i] = fmaxf(s + bimg[n], 0.f);
}

// ---------------- persistent LSTM recurrence (R12, verbatim) ----------------
#define PB_BYTES 131072
#define PA_BYTES 65536
#define PX_BYTES 33792
#define PS_SMEM  (PB_BYTES + PA_BYTES + PX_BYTES)

__global__ __launch_bounds__(512)
void lstm_persist_kernel(const int* __restrict__ cap, float* __restrict__ out)
{
    extern __shared__ __align__(1024) char smem[];
    const uint32_t sbB = smem_u32(smem);
    const uint32_t sbA = sbB + PB_BYTES;
    const uint32_t sbX = sbA + PA_BYTES;
    float* sx = (float*)(smem + PB_BYTES + PA_BYTES);

    const int t = threadIdx.x;
    const int lane = t & 31;
    const int wid = t >> 5;
    const int wm = wid >> 2;
    const int wn = wid & 3;
    const int mb = blockIdx.x & 15;
    const int nb = blockIdx.x >> 4;
    const int m0 = mb * 64;
    const int n0 = nb * 128;
    const int hcol = nb * 32;

#pragma unroll
    for (int i = 0; i < 16; ++i) {
        const int ug = i * 512 + t;
        const int r = ug >> 6, u = ug & 63;
        cp_async16(sbB + (uint32_t)((r * 64 + (u & ~7) + ((u & 7) ^ (r & 7))) * 16),
                   g_whh + (size_t)(n0 + r) * 512 + u * 8);
    }
    asm volatile("cp.async.commit_group;" ::: "memory");

    const int mhi = lane >> 4;
    const int kq  = lane >> 3;
    const int rA = wm * 16 + ((lane >> 3) & 1) * 8 + (lane & 7);
    int rB[4];
#pragma unroll
    for (int q = 0; q < 4; ++q)
        rB[q] = q * 32 + wn * 8 + (lane & 7);

    const int jl0 = wn * 8 + (lane & 3) * 2;

    float creg[2][2];
    float img_r[2][2];
#pragma unroll
    for (int h = 0; h < 2; ++h) {
        const int m = m0 + wm * 16 + (lane >> 2) + h * 8;
        creg[h][0] = 0.f; creg[h][1] = 0.f;
        img_r[h][0] = g_img[m * HDIM + hcol + jl0];
        img_r[h][1] = g_img[m * HDIM + hcol + jl0 + 1];
    }

    auto issueX = [&](int ts) {
        const int* capt = cap + ts * BATCH + m0;
#pragma unroll
        for (int i = 0; i < 4; ++i) {
            const int ug = i * 512 + t;
            const int r = ug >> 5, w = ug & 31;
            const int ci = __ldg(capt + r);
            cp_async16(sbX + (uint32_t)(r * 528 + w * 16),
                       g_proj + (size_t)ci * G4 + n0 + w * 4);
        }
        asm volatile("cp.async.commit_group;" ::: "memory");
    };

    issueX(0);

    asm volatile("cp.async.wait_group 1;" ::: "memory");
    __syncthreads();

#pragma unroll 1
    for (int ts = 0; ts < TSTEPS; ++ts) {
        const __nv_bfloat16* hhi_r = g_hhi[ts & 1];
        const __nv_bfloat16* hlo_r = g_hlo[ts & 1];
        __nv_bfloat16* hhi_w = g_hhi[(ts & 1) ^ 1];
        __nv_bfloat16* hlo_w = g_hlo[(ts & 1) ^ 1];
        float* out_t = out + (size_t)ts * BATCH * HDIM;

        if (ts) grid_barrier();

#pragma unroll
        for (int i = 0; i < 8; ++i) {
            const int ug = i * 512 + t;
            const int buf = ug >> 11;
            const int idx = ug & 2047;
            const int r = idx >> 5, u = idx & 31;
            const __nv_bfloat16* src = (buf ? hlo_r : hhi_r) + (size_t)(m0 + r) * HDIM + u * 8;
            cp_async16(sbA + (uint32_t)(buf * 32768 + (r * 32 + (u & ~7) + ((u & 7) ^ (r & 7))) * 16), src);
        }
        asm volatile("cp.async.commit_group;" ::: "memory");
        asm volatile("cp.async.wait_group 0;" ::: "memory");
        __syncthreads();

        float acc[4][4];
#pragma unroll
        for (int j = 0; j < 4; ++j)
#pragma unroll
            for (int r = 0; r < 4; ++r) acc[j][r] = 0.f;

#pragma unroll 1
        for (int kc = 0; kc < 4; ++kc) {
#pragma unroll
            for (int ksp = 0; ksp < 2; ++ksp) {
                uint32_t bhi[4][4], blo[4][4];
#pragma unroll
                for (int q = 0; q < 4; ++q) {
                    const int r = rB[q];
                    const uint32_t sw = (uint32_t)(((ksp * 4 + kq) ^ (r & 7)) * 16);
                    ldm_x4(bhi[q], sbB + (uint32_t)((r * 64 + kc * 8) * 16) + sw);
                    ldm_x4(blo[q], sbB + (uint32_t)((r * 64 + 32 + kc * 8) * 16) + sw);
                }
#pragma unroll
                for (int ks2 = 0; ks2 < 2; ++ks2) {
                    const int ks = ksp * 2 + ks2;
                    uint32_t ahi[4], alo[4];
                    const uint32_t aoff = (uint32_t)((rA * 32 + kc * 8 + ((ks * 2 + mhi) ^ (rA & 7))) * 16);
                    ldm_x4(ahi, sbA + aoff);
                    ldm_x4(alo, sbA + 32768 + aoff);
#pragma unroll
                    for (int q = 0; q < 4; ++q) {
                        mma_bf16(acc[q], ahi, bhi[q] + ks2 * 2);
                        mma_bf16(acc[q], alo, bhi[q] + ks2 * 2);
                        mma_bf16(acc[q], ahi, blo[q] + ks2 * 2);
                    }
                }
            }
        }

#pragma unroll
        for (int h = 0; h < 2; ++h) {
            const int m = m0 + wm * 16 + (lane >> 2) + h * 8;
            const float* xr = sx + (m - m0) * 132;
            float hn[2];
#pragma unroll
            for (int jj = 0; jj < 2; ++jj) {
                const int jl = jl0 + jj;
                const int rs = h * 2 + jj;
                const float gi = acc[0][rs] + xr[jl];
                const float gf = acc[1][rs] + xr[32 + jl];
                const float gg = acc[2][rs] + xr[64 + jl];
                const float go = acc[3][rs] + xr[96 + jl];
                const float iv = 1.f / (1.f + expf(-gi));
                const float fv = 1.f / (1.f + expf(-gf));
                const float gv = tanhf(gg);
                const float ov = 1.f / (1.f + expf(-go));
                const float cn = fv * creg[h][jj] + iv * gv;
                hn[jj] = ov * tanhf(cn);
                creg[h][jj] = cn;
            }
            const int idx = m * HDIM + hcol + jl0;
            const __nv_bfloat16 h0 = __float2bfloat16(hn[0]);
            const __nv_bfloat16 h1 = __float2bfloat16(hn[1]);
            __nv_bfloat162 hhp; hhp.x = h0; hhp.y = h1;
            __nv_bfloat162 hlp;
            hlp.x = __float2bfloat16(hn[0] - __bfloat162float(h0));
            hlp.y = __float2bfloat16(hn[1] - __bfloat162float(h1));
            *(__nv_bfloat162*)&hhi_w[idx] = hhp;
            *(__nv_bfloat162*)&hlo_w[idx] = hlp;
            float2 ov2 = make_float2(hn[0] + img_r[h][0], hn[1] + img_r[h][1]);
            *(float2*)&out_t[idx] = ov2;
        }

        if (ts + 1 < TSTEPS) {
            __syncthreads();
            issueX(ts + 1);
        }
    }
}

// ---------------- all prepacking in ONE kernel -------------------------------
#define S_EMB  ((size_t)VOCAB * HDIM)
#define S_W    ((size_t)G4 * HDIM)
#define S_HC   ((size_t)BATCH * HDIM)
#define S_IMG  ((size_t)BATCH * IMGD)
#define S_WIMG ((size_t)HDIM * IMGD)
#define PREP_TOTAL (S_EMB + 2 * S_W + S_HC + G4 + S_IMG + S_WIMG)

__global__ void prep_all_kernel(const float* __restrict__ emb,
                                const float* __restrict__ Wih,
                                const float* __restrict__ Whh,
                                const float* __restrict__ bih,
                                const float* __restrict__ bhh,
                                const float* __restrict__ img,
                                const float* __restrict__ Wimg)
{
    const size_t i = (size_t)blockIdx.x * 256 + threadIdx.x;
    if (i < S_EMB) {
        const float v = emb[i];
        const __nv_bfloat16 h = __float2bfloat16(v);
        g_ehi[i] = h;
        g_elo[i] = __float2bfloat16(v - __bfloat162float(h));
    } else if (i < S_EMB + 2 * S_W) {
        const size_t ii = i - S_EMB;
        const int which = (int)(ii / S_W);
        const int idx = (int)(ii % S_W);
        const int p = idx >> 8, k = idx & 255;
        const int nt = p >> 7, q = (p >> 5) & 3, j = p & 31;
        const int orig = q * 256 + nt * 32 + j;
        const float* W = which ? Whh : Wih;
        __nv_bfloat16* Wd = which ? g_whh : g_wih;
        const float v = W[orig * 256 + k];
        const __nv_bfloat16 h = __float2bfloat16(v);
        Wd[p * 512 + k] = h;
        Wd[p * 512 + 256 + k] = __float2bfloat16(v - __bfloat162float(h));
    } else if (i < S_EMB + 2 * S_W + S_HC) {
        const int idx = (int)(i - S_EMB - 2 * S_W);
        g_hhi[0][idx] = __float2bfloat16(0.f);
        g_hlo[0][idx] = __float2bfloat16(0.f);
    } else if (i < S_EMB + 2 * S_W + S_HC + G4) {
        const int p = (int)(i - S_EMB - 2 * S_W - S_HC);
        const int nt = p >> 7, q = (p >> 5) & 3, j = p & 31;
        const int orig = q * 256 + nt * 32 + j;
        g_biasp[p] = bih[orig] + bhh[orig];
    } else if (i < S_EMB + 2 * S_W + S_HC + G4 + S_IMG) {
        const size_t idx = i - (S_EMB + 2 * S_W + S_HC + G4);
        const float v = img[idx];
        const __nv_bfloat16 h = __float2bfloat16(v);
        g_ihi[idx] = h;
        g_ilo[idx] = __float2bfloat16(v - __bfloat162float(h));
    } else if (i < PREP_TOTAL) {
        const size_t idx = i - (S_EMB + 2 * S_W + S_HC + G4 + S_IMG);
        const int n = (int)(idx >> 11);     // / IMGD
        const int k = (int)(idx & 2047);
        const float v = Wimg[idx];
        const __nv_bfloat16 h = __float2bfloat16(v);
        g_wimgp[(size_t)n * 4096 + k] = h;
        g_wimgp[(size_t)n * 4096 + 2048 + k] = __float2bfloat16(v - __bfloat162float(h));
    }
}

// ---------------- launcher ---------------------------------------------------
extern "C" void kernel_launch(void* const* d_in, const int* in_sizes, int n_in,
                              void* d_out, int out_size)
{
    const float* img  = (const float*)d_in[0];
    const int*   cap  = (const int*)  d_in[1];
    const float* Wimg = (const float*)d_in[2];
    const float* bimg = (const float*)d_in[3];
    const float* emb  = (const float*)d_in[4];
    const float* Wih  = (const float*)d_in[5];
    const float* Whh  = (const float*)d_in[6];
    const float* bih  = (const float*)d_in[7];
    const float* bhh  = (const float*)d_in[8];
    float* out = (float*)d_out;

    float* p_proj;  cudaGetSymbolAddress((void**)&p_proj,  g_proj);
    float* p_ipart; cudaGetSymbolAddress((void**)&p_ipart, g_imgpart);

    cudaFuncSetAttribute(proj_mma_kernel, cudaFuncAttributeMaxDynamicSharedMemorySize, XG_SMEM);
    cudaFuncSetAttribute(img_mma_kernel,  cudaFuncAttributeMaxDynamicSharedMemorySize, XG_SMEM);
    cudaFuncSetAttribute(lstm_persist_kernel, cudaFuncAttributeMaxDynamicSharedMemorySize, PS_SMEM);

    prep_all_kernel<<<(int)((PREP_TOTAL + 255) / 256), 256>>>(emb, Wih, Whh, bih, bhh, img, Wimg);

    {
        dim3 grid(BATCH / 128, HDIM / 128, 4);   // 8 x 2 x 4 = 64 CTAs
        img_mma_kernel<<<grid, 256, XG_SMEM>>>(p_ipart);
    }
    img_reduce_kernel<<<(BATCH * HDIM) / 256, 256>>>(bimg);

    {
        dim3 grid(VOCAB / 128, G4 / 128);   // 250 x 8
        proj_mma_kernel<<<grid, 256, XG_SMEM>>>(p_proj);
    }

    lstm_persist_kernel<<<128, 512, PS_SMEM>>>(cap, out);
}